// round 8
// baseline (speedup 1.0000x reference)
#include <cuda_runtime.h>

#define THREADS 256
#define OPT 16                      // outputs per thread (8 pairs)
#define TILE (THREADS * OPT)        // 4096 outputs per block
#define PTAPS 31                    // pair-taps actually needed for K=61
#define NPAIR ((TILE + 64) / 2)     // 2080 data pairs staged
#define NSLOT (NPAIR + NPAIR / 8)   // skewed slots (pair i -> slot i + i/8)

typedef unsigned long long ull;

__device__ __forceinline__ ull pk2(float lo, float hi) {
    ull r; asm("mov.b64 %0, {%1, %2};" : "=l"(r) : "f"(lo), "f"(hi)); return r;
}
__device__ __forceinline__ void upk2(ull v, float& lo, float& hi) {
    asm("mov.b64 {%0, %1}, %2;" : "=f"(lo), "=f"(hi) : "l"(v));
}
__device__ __forceinline__ ull ffma2(ull a, ull b, ull c) {
    ull d; asm("fma.rn.f32x2 %0, %1, %2, %3;" : "=l"(d) : "l"(a), "l"(b), "l"(c)); return d;
}
__device__ __forceinline__ constexpr int skew(int c) { return c + (c >> 3); }

__global__ __launch_bounds__(THREADS) void fir7_kernel(
    const float* __restrict__ u, const float* __restrict__ kern,
    float* __restrict__ out, int cols, int out_cols, int K)
{
    __shared__ ull        s_p[NSLOT];   // skewed pair array
    __shared__ ulonglong2 s_w[PTAPS + 1]; // (WE[t], WO[t]); +1 pad so hoisted OOB prefetch is safe

    const int tid  = threadIdx.x;
    const int row  = blockIdx.y;
    const int base = blockIdx.x * TILE;
    const float* urow = u + (size_t)row * cols;

    // w[k] = kern[K-1-k] reversed, zero-padded.
    // WE[t] = (w[2t], w[2t+1]) : even outputs.  WO[t] = (w[2t-1], w[2t]) : odd outputs.
    if (tid < PTAPS + 1) {
        const int t = tid;
        const float we0 = (2*t     < K) ? kern[K - 1 - 2*t]       : 0.0f;
        const float we1 = (2*t + 1 < K) ? kern[K - 1 - (2*t + 1)] : 0.0f;
        const float wo0 = (2*t >= 1 && 2*t - 1 < K) ? kern[K - 1 - (2*t - 1)] : 0.0f;
        s_w[t] = make_ulonglong2(pk2(we0, we1), pk2(wo0, we0));
    }

    // Stage input tile into skewed pair layout (pair i at slot i + i/8).
    for (int q = tid; q < NPAIR / 2; q += THREADS) {
        const int gi = base + 4 * q;
        float4 v;
        if (gi + 3 < cols) {
            v = *reinterpret_cast<const float4*>(urow + gi);
        } else {
            v.x = (gi + 0 < cols) ? urow[gi + 0] : 0.0f;
            v.y = (gi + 1 < cols) ? urow[gi + 1] : 0.0f;
            v.z = (gi + 2 < cols) ? urow[gi + 2] : 0.0f;
            v.w = (gi + 3 < cols) ? urow[gi + 3] : 0.0f;
        }
        const int s = 2 * q + (q >> 2);     // slot(2q) = 2q + (2q>>3)
        s_p[s + 0] = pk2(v.x, v.y);
        s_p[s + 1] = pk2(v.z, v.w);
    }
    __syncthreads();

    const int bslot = 9 * tid;              // slot(8*tid + c) = 9*tid + skew(c)

    // Rotating window: invariant at tap t -> win[(t+r)&7] = P[8*tid + t + r].
    ull win[8];
    #pragma unroll
    for (int r = 0; r < 8; ++r) win[r] = s_p[bslot + skew(r)];

    ull Ae[8], Ao[8];
    #pragma unroll
    for (int r = 0; r < 8; ++r) { Ae[r] = 0ull; Ao[r] = 0ull; }

    #pragma unroll
    for (int t = 0; t < PTAPS; ++t) {
        const ulonglong2 W = s_w[t];        // LDS.128 broadcast
        #pragma unroll
        for (int r = 0; r < 8; ++r) {
            const ull p = win[(t + r) & 7]; // compile-time index, no MOV chain
            Ae[r] = ffma2(p, W.x, Ae[r]);
            Ao[r] = ffma2(p, W.y, Ao[r]);
        }
        if (t < PTAPS - 1)
            win[t & 7] = s_p[bslot + skew(t + 8)];   // in-place refill, 1 LDS.64/tap
    }

    // Horizontal sums -> 16 consecutive outputs.
    float res[16];
    #pragma unroll
    for (int r = 0; r < 8; ++r) {
        float e0, e1, d0, d1;
        upk2(Ae[r], e0, e1); upk2(Ao[r], d0, d1);
        res[2*r + 0] = e0 + e1;
        res[2*r + 1] = d0 + d1;
    }

    const int oc = base + tid * OPT;        // 16-aligned
    float* orow = out + (size_t)row * out_cols;
    if (oc + OPT - 1 < out_cols) {
        #pragma unroll
        for (int q = 0; q < OPT / 4; ++q) {
            float4 v; v.x = res[4*q]; v.y = res[4*q+1]; v.z = res[4*q+2]; v.w = res[4*q+3];
            *reinterpret_cast<float4*>(orow + oc + 4*q) = v;
        }
    } else {
        #pragma unroll
        for (int k = 0; k < OPT; ++k)
            if (oc + k < out_cols) orow[oc + k] = res[k];
    }
}

extern "C" void kernel_launch(void* const* d_in, const int* in_sizes, int n_in,
                              void* d_out, int out_size)
{
    const float* u    = (const float*)d_in[0];
    const float* kern = (const float*)d_in[1];
    float*       out  = (float*)d_out;

    const int S0 = in_sizes[0];
    const int K  = in_sizes[1];
    const int rows     = (S0 - out_size) / (K - 1);
    const int cols     = S0 / rows;
    const int out_cols = cols - K + 1;

    dim3 grid((out_cols + TILE - 1) / TILE, rows);
    fir7_kernel<<<grid, THREADS>>>(u, kern, out, cols, out_cols, K);
}